// round 7
// baseline (speedup 1.0000x reference)
#include <cuda_runtime.h>
#include <math.h>

#define NN      1023
#define NLEAVES 512
#define HD      300
#define GP      320           // padded per-gate width (strip layout)
#define NBP     960           // 3 * GP (strip layout, for XX / prologue)
#define NBLK    296           // 2 blocks/SM
#define NTHR    256
#define NJT     19            // ceil(300/16) j-tiles
#define WIROW   1216          // NJT * 64 floats per k-row of interleaved weights
#define WIK     320           // padded K for interleaved weights

typedef unsigned long long ull;

// ---------------- static device scratch ----------------
__device__ float g_Wxp[HD * NBP];       // packed W_ix|W_fx|W_ux (strips)
__device__ float g_Whi[WIK * WIROW];    // interleaved recurrent weights [k][jt][jj*4+g]
__device__ float g_bsum[NBP];           // b_*x + b_*h (strips)
__device__ float g_XX[NN * NBP];        // x @ Wxp
__device__ float g_h[NN * HD];
__device__ float g_c[NN * HD];
__device__ float g_loss[NN];
__device__ float g_logp_scratch[NN * 5];
__device__ unsigned g_flags[NBLK];      // per-block barrier flags

// ---------------- f32x2 helpers ----------------
static __device__ __forceinline__ ull pack2(float x, float y) {
    ull r;
    asm("mov.b64 %0, {%1, %2};" : "=l"(r) : "f"(x), "f"(y));
    return r;
}
static __device__ __forceinline__ void unpack2(ull v, float &x, float &y) {
    asm("mov.b64 {%0, %1}, %2;" : "=f"(x), "=f"(y) : "l"(v));
}
static __device__ __forceinline__ void ffma2(ull &d, ull a, ull b) {
    asm("fma.rn.f32x2 %0, %1, %2, %0;" : "+l"(d) : "l"(a), "l"(b));
}
static __device__ __forceinline__ float sigf(float x) {
    return 1.0f / (1.0f + expf(-x));
}

// ---------------- one-hop all-poll grid barrier ----------------
static __device__ __forceinline__ void gbar(unsigned target) {
    __syncthreads();
    if (threadIdx.x == 0) {
        __threadfence();                                  // release this block's writes
        ((volatile unsigned*)g_flags)[blockIdx.x] = target;
    }
    for (int i = threadIdx.x; i < NBLK; i += NTHR)
        while (((volatile unsigned*)g_flags)[i] < target) { }
    __syncthreads();
    if (threadIdx.x == 0) __threadfence();                // acquire (L1 invalidate)
    __syncthreads();
}

// ---------------- pack weights ----------------
__global__ void pack_w(const float* __restrict__ Wix, const float* __restrict__ Wfx,
                       const float* __restrict__ Wux, const float* __restrict__ Wih,
                       const float* __restrict__ Wfh, const float* __restrict__ Wuh,
                       const float* __restrict__ bix, const float* __restrict__ bfx,
                       const float* __restrict__ bux, const float* __restrict__ bih,
                       const float* __restrict__ bfh, const float* __restrict__ buh)
{
    int idx = blockIdx.x * blockDim.x + threadIdx.x;
    // strip layout for prologue (x-weights)
    if (idx < HD * NBP) {
        int k = idx / NBP, c = idx % NBP;
        int g = c / GP, j = c % GP;
        float vx = 0.f;
        if (j < HD) {
            const float* wx = (g == 0) ? Wix : (g == 1) ? Wfx : Wux;
            vx = wx[k * HD + j];
        }
        g_Wxp[idx] = vx;
    }
    // interleaved layout for recurrent weights: [k][jt][jj*4 + g]
    if (idx < WIK * WIROW) {
        int k = idx / WIROW, rem = idx % WIROW;
        int jt = rem / 64, q = rem % 64;
        int jj = q >> 2, g = q & 3;
        float v = 0.f;
        int j = jt * 16 + jj;
        if (g < 3 && k < HD && j < HD) {
            const float* wh = (g == 0) ? Wih : (g == 1) ? Wfh : Wuh;
            v = wh[k * HD + j];
        }
        g_Whi[idx] = v;
    }
    if (idx < NBP) {
        int g = idx / GP, j = idx % GP;
        float v = 0.f;
        if (j < HD) {
            const float* bx = (g == 0) ? bix : (g == 1) ? bfx : bux;
            const float* bh = (g == 0) ? bih : (g == 1) ? bfh : buh;
            v = bx[j] + bh[j];
        }
        g_bsum[idx] = v;
    }
}

// ---------------- prologue GEMM (64x64 tiles, f32x2, double-buffered) -------------
static __device__ __forceinline__ void ld_stage_regs(
    const float* __restrict__ aptr, bool aval,
    const float* __restrict__ bptr, int kb, int akq, int bk,
    float4 &a0, float4 &a1, float4 &b0, float4 &b1)
{
    const float4 z = make_float4(0.f, 0.f, 0.f, 0.f);
    int gk0 = kb + (akq << 2), gk1 = gk0 + 16;
    a0 = (aval && gk0 < HD) ? *(const float4*)(aptr + gk0) : z;
    a1 = (aval && gk1 < HD) ? *(const float4*)(aptr + gk1) : z;
    int gb0 = kb + bk, gb1 = gb0 + 16;
    b0 = (gb0 < HD) ? *(const float4*)(bptr + (size_t)gb0 * NBP) : z;
    b1 = (gb1 < HD) ? *(const float4*)(bptr + (size_t)gb1 * NBP) : z;
}

__device__ __noinline__ void gemm_stage(const float* __restrict__ src,
                                        const int* __restrict__ rowIdx, int M,
                                        const float* __restrict__ B,
                                        float* __restrict__ out,
                                        float (&As)[2][32][68],
                                        float (&Bs)[2][32][64])
{
    const int tid = threadIdx.x;
    const int tx = tid & 15, ty = tid >> 4;
    const int am  = tid & 63;
    const int akq = tid >> 6;
    const int bn4 = (tid & 15) << 2;
    const int bk  = tid >> 4;

    const int ntm = (M + 63) >> 6;
    const int ntiles = ntm * 15;
    const int S = 10;

    for (int t = blockIdx.x; t < ntiles; t += NBLK) {
        const int m0 = (t / 15) << 6;
        const int n0 = (t % 15) << 6;

        const bool aval = (m0 + am < M);
        const int  arow = aval ? rowIdx[m0 + am] : 0;
        const float* __restrict__ aptr = src + (size_t)arow * HD;
        const float* __restrict__ bptr = B + n0 + bn4;

        const bool act = (m0 + (ty << 2) < M);

        float4 a0, a1, b0, b1;
        ld_stage_regs(aptr, aval, bptr, 0, akq, bk, a0, a1, b0, b1);
        {
            int ka = akq << 2;
            As[0][ka + 0][am] = a0.x; As[0][ka + 1][am] = a0.y;
            As[0][ka + 2][am] = a0.z; As[0][ka + 3][am] = a0.w;
            As[0][16 + ka + 0][am] = a1.x; As[0][16 + ka + 1][am] = a1.y;
            As[0][16 + ka + 2][am] = a1.z; As[0][16 + ka + 3][am] = a1.w;
            *(float4*)&Bs[0][bk][bn4]      = b0;
            *(float4*)&Bs[0][bk + 16][bn4] = b1;
        }
        __syncthreads();

        ull acc[4][2];
#pragma unroll
        for (int i = 0; i < 4; i++) { acc[i][0] = pack2(0.f, 0.f); acc[i][1] = pack2(0.f, 0.f); }

        for (int s = 0; s < S; s++) {
            const int p = s & 1;

            if (s + 1 < S)
                ld_stage_regs(aptr, aval, bptr, (s + 1) << 5, akq, bk, a0, a1, b0, b1);

            if (act) {
                float4 a_c = *(const float4*)&As[p][0][ty << 2];
                ulonglong2 b_c = *(const ulonglong2*)&Bs[p][0][tx << 2];
#pragma unroll
                for (int k = 0; k < 32; k++) {
                    float4 a_n;
                    ulonglong2 b_n;
                    if (k < 31) {
                        a_n = *(const float4*)&As[p][k + 1][ty << 2];
                        b_n = *(const ulonglong2*)&Bs[p][k + 1][tx << 2];
                    } else {
                        a_n = make_float4(0.f, 0.f, 0.f, 0.f);
                        b_n.x = 0; b_n.y = 0;
                    }
                    ull ap;
                    ap = pack2(a_c.x, a_c.x); ffma2(acc[0][0], ap, b_c.x); ffma2(acc[0][1], ap, b_c.y);
                    ap = pack2(a_c.y, a_c.y); ffma2(acc[1][0], ap, b_c.x); ffma2(acc[1][1], ap, b_c.y);
                    ap = pack2(a_c.z, a_c.z); ffma2(acc[2][0], ap, b_c.x); ffma2(acc[2][1], ap, b_c.y);
                    ap = pack2(a_c.w, a_c.w); ffma2(acc[3][0], ap, b_c.x); ffma2(acc[3][1], ap, b_c.y);
                    a_c = a_n; b_c = b_n;
                }
            }

            if (s + 1 < S) {
                const int q = p ^ 1;
                int ka = akq << 2;
                As[q][ka + 0][am] = a0.x; As[q][ka + 1][am] = a0.y;
                As[q][ka + 2][am] = a0.z; As[q][ka + 3][am] = a0.w;
                As[q][16 + ka + 0][am] = a1.x; As[q][16 + ka + 1][am] = a1.y;
                As[q][16 + ka + 2][am] = a1.z; As[q][16 + ka + 3][am] = a1.w;
                *(float4*)&Bs[q][bk][bn4]      = b0;
                *(float4*)&Bs[q][bk + 16][bn4] = b1;
            }
            __syncthreads();
        }

        if (act) {
#pragma unroll
            for (int i = 0; i < 4; i++) {
                int gm = m0 + (ty << 2) + i;
                if (gm < M) {
                    float x0, x1, x2, x3;
                    unpack2(acc[i][0], x0, x1);
                    unpack2(acc[i][1], x2, x3);
                    *(float4*)&out[(size_t)gm * NBP + n0 + (tx << 2)] =
                        make_float4(x0, x1, x2, x3);
                }
            }
        }
    }
}

// ---------------- fused level kernel: per-tile GEMM + LSTM cell epilogue ----------
// Tile = 16 child-rows (8 nodes) x 16 j-triples (48 real cols). Full K in regs.
__device__ __noinline__ void level_fused(int base, int W, const int* __restrict__ children,
                                         float (&As2)[32][16], float (&Bs2)[32][64],
                                         float (&Cs)[16][64], int (&rowArr)[16])
{
    const int tid = threadIdx.x;
    const int M = 2 * W;
    const int nmc = (M + 15) >> 4;
    const int ntiles = nmc * NJT;

    const int rA = tid >> 3;            // A-load row (0..15) for tid<128
    const int qA = tid & 7;             // A-load k-quad
    const int kB = tid >> 3;            // B-load k (0..31)
    const int fB = (tid & 7) << 1;      // B-load: float4 pair index

    const int row = tid & 15;           // compute row
    const int jg  = tid >> 4;           // compute j-group (0..15)

    for (int t = blockIdx.x; t < ntiles; t += NBLK) {
        const int mc = t / NJT, jt = t % NJT;

        if (tid < 16) {
            int m = (mc << 4) + tid;
            int r = -1;
            if (m < M) {
                int n = m >> 1;
                r = children[2 * (base + n) + (m & 1)];
            }
            rowArr[tid] = r;
        }
        __syncthreads();

        const float* __restrict__ bbase = g_Whi + jt * 64 + (fB << 2);

        // prefetch chunk 0
        float4 aR = make_float4(0.f, 0.f, 0.f, 0.f);
        float4 bR0, bR1;
        if (tid < 128) {
            int r = rowArr[rA];
            int k = qA << 2;
            if (r >= 0 && k < HD) aR = *(const float4*)(g_h + (size_t)r * HD + k);
        }
        bR0 = *(const float4*)(bbase + (size_t)kB * WIROW);
        bR1 = *(const float4*)(bbase + (size_t)kB * WIROW + 4);

        ull acc01 = pack2(0.f, 0.f);
        float acc2 = 0.f;

#pragma unroll 1
        for (int c = 0; c < 10; c++) {
            if (tid < 128) {
                int ka = qA << 2;
                As2[ka + 0][rA] = aR.x; As2[ka + 1][rA] = aR.y;
                As2[ka + 2][rA] = aR.z; As2[ka + 3][rA] = aR.w;
            }
            *(float4*)&Bs2[kB][fB << 2]       = bR0;
            *(float4*)&Bs2[kB][(fB << 2) + 4] = bR1;
            __syncthreads();

            if (c < 9) {
                int k0 = (c + 1) << 5;
                aR = make_float4(0.f, 0.f, 0.f, 0.f);
                if (tid < 128) {
                    int r = rowArr[rA];
                    int k = k0 + (qA << 2);
                    if (r >= 0 && k < HD) aR = *(const float4*)(g_h + (size_t)r * HD + k);
                }
                bR0 = *(const float4*)(bbase + (size_t)(k0 + kB) * WIROW);
                bR1 = *(const float4*)(bbase + (size_t)(k0 + kB) * WIROW + 4);
            }

#pragma unroll
            for (int k = 0; k < 32; k++) {
                float av = As2[k][row];
                float4 b = *(const float4*)&Bs2[k][jg << 2];
                ffma2(acc01, pack2(av, av), pack2(b.x, b.y));
                acc2 = fmaf(av, b.z, acc2);
            }
            __syncthreads();
        }

        // spill tile to smem for the cross-row/cross-gate epilogue
        {
            float x0, x1;
            unpack2(acc01, x0, x1);
            Cs[row][(jg << 2) + 0] = x0;
            Cs[row][(jg << 2) + 1] = x1;
            Cs[row][(jg << 2) + 2] = acc2;
        }
        __syncthreads();

        if (tid < 128) {
            int p  = tid >> 4;          // local node 0..7
            int jj = tid & 15;
            int n  = (mc << 3) + p;
            int j  = jt * 16 + jj;
            if (n < W && j < HD) {
                int tn = base + n;
                float i_raw = Cs[2 * p][(jj << 2)]     + Cs[2 * p + 1][(jj << 2)];
                float f0    = Cs[2 * p][(jj << 2) + 1];
                float f1    = Cs[2 * p + 1][(jj << 2) + 1];
                float u_raw = Cs[2 * p][(jj << 2) + 2] + Cs[2 * p + 1][(jj << 2) + 2];
                const float* xx = g_XX + (size_t)tn * NBP;
                float xi = xx[j]          + g_bsum[j];
                float xf = xx[GP + j]     + g_bsum[GP + j];
                float xu = xx[2 * GP + j] + g_bsum[2 * GP + j];
                float i = sigf(xi + i_raw);
                float o = sigf(xf + f0 + f1);
                float u = sigf(xu + u_raw);
                float ff0 = sigf(xf + f0);
                float ff1 = sigf(xf + f1);
                int c0 = children[2 * tn], c1 = children[2 * tn + 1];
                float cc = i * u + ff0 * g_c[c0 * HD + j] + ff1 * g_c[c1 * HD + j];
                g_c[tn * HD + j] = cc;
                g_h[tn * HD + j] = o * tanhf(cc);
            }
        }
        __syncthreads();

        // reset accumulators for the next grid-strided tile
        acc01 = pack2(0.f, 0.f);
        acc2 = 0.f;
    }
}

// ---------------- persistent mega-kernel ----------------
__global__ __launch_bounds__(NTHR, 2) void mega_kernel(
    const int* __restrict__ word_ids, const int* __restrict__ labels,
    const int* __restrict__ children, const float* __restrict__ emb,
    const float* __restrict__ Wout, const float* __restrict__ bout,
    float* __restrict__ out, int out_size)
{
    __shared__ float As[2][32][68];
    __shared__ __align__(16) float Bs[2][32][64];
    __shared__ float As2[32][16];
    __shared__ __align__(16) float Bs2[32][64];
    __shared__ __align__(16) float Cs[16][64];
    __shared__ int rowArr[16];
    __shared__ float sred[NTHR];

    unsigned barno = 0;

    // ---- stage 1: prologue GEMM ----
    gemm_stage(emb, word_ids, NN, g_Wxp, g_XX, As, Bs);
    gbar(++barno);

    // ---- stage 2: leaves ----
    for (int idx = blockIdx.x * NTHR + threadIdx.x; idx < NLEAVES * HD; idx += NBLK * NTHR) {
        int t = idx / HD, j = idx % HD;
        const float* xx = g_XX + (size_t)t * NBP;
        float i = sigf(xx[j]          + g_bsum[j]);
        float o = sigf(xx[GP + j]     + g_bsum[GP + j]);
        float u = sigf(xx[2 * GP + j] + g_bsum[2 * GP + j]);
        float c = i * u;
        g_c[t * HD + j] = c;
        g_h[t * HD + j] = o * tanhf(c);
    }
    gbar(++barno);

    // ---- stage 3: 9 fused levels ----
    const int bases[9]  = {512, 768, 896, 960, 992, 1008, 1016, 1020, 1022};
    const int widths[9] = {256, 128, 64, 32, 16, 8, 4, 2, 1};
#pragma unroll 1
    for (int l = 0; l < 9; l++) {
        level_fused(bases[l], widths[l], children, As2, Bs2, Cs, rowArr);
        gbar(++barno);
    }

    // ---- stage 4: logits + log_softmax + per-node loss ----
    {
        int gw = (blockIdx.x * NTHR + threadIdx.x) >> 5;
        int lane = threadIdx.x & 31;
        if (gw < NN) {
            const float* h = g_h + (size_t)gw * HD;
            float a0 = 0.f, a1 = 0.f, a2 = 0.f, a3 = 0.f, a4 = 0.f;
            for (int j = lane; j < HD; j += 32) {
                float hv = h[j];
                const float* w = Wout + j * 5;
                a0 += hv * w[0]; a1 += hv * w[1]; a2 += hv * w[2];
                a3 += hv * w[3]; a4 += hv * w[4];
            }
#pragma unroll
            for (int off = 16; off > 0; off >>= 1) {
                a0 += __shfl_down_sync(0xffffffffu, a0, off);
                a1 += __shfl_down_sync(0xffffffffu, a1, off);
                a2 += __shfl_down_sync(0xffffffffu, a2, off);
                a3 += __shfl_down_sync(0xffffffffu, a3, off);
                a4 += __shfl_down_sync(0xffffffffu, a4, off);
            }
            if (lane == 0) {
                float lg[5] = {a0 + bout[0], a1 + bout[1], a2 + bout[2],
                               a3 + bout[3], a4 + bout[4]};
                float mx = lg[0];
#pragma unroll
                for (int l = 1; l < 5; l++) mx = fmaxf(mx, lg[l]);
                float se = 0.f;
#pragma unroll
                for (int l = 0; l < 5; l++) se += expf(lg[l] - mx);
                float lse = mx + logf(se);
                float* dst = (out_size >= NN * 5) ? (out + (size_t)gw * 5)
                                                  : (g_logp_scratch + (size_t)gw * 5);
#pragma unroll
                for (int l = 0; l < 5; l++) dst[l] = lg[l] - lse;
                g_loss[gw] = -(lg[labels[gw]] - lse);
            }
        }
    }

    // ---- final barrier: arrival-only; block 0 reduces loss and resets flags ----
    {
        const unsigned fin = ++barno;
        __syncthreads();
        if (threadIdx.x == 0) {
            __threadfence();
            ((volatile unsigned*)g_flags)[blockIdx.x] = fin;
        }
        if (blockIdx.x != 0) return;

        for (int i = threadIdx.x; i < NBLK; i += NTHR)
            while (((volatile unsigned*)g_flags)[i] < fin) { }
        __syncthreads();
        if (threadIdx.x == 0) __threadfence();
        __syncthreads();

        float v = 0.f;
        for (int i = threadIdx.x; i < NN; i += NTHR) v += g_loss[i];
        sred[threadIdx.x] = v;
        __syncthreads();
        for (int st = NTHR / 2; st > 0; st >>= 1) {
            if (threadIdx.x < st) sred[threadIdx.x] += sred[threadIdx.x + st];
            __syncthreads();
        }
        if (threadIdx.x == 0) {
            if (out_size > NN * 5)      out[NN * 5] = sred[0];
            else if (out_size < NN * 5) out[0]      = sred[0];
        }
        __syncthreads();

        for (int i = threadIdx.x; i < NBLK; i += NTHR)
            ((volatile unsigned*)g_flags)[i] = 0;
        if (threadIdx.x == 0) __threadfence();
    }
}

// ---------------- launch ----------------
extern "C" void kernel_launch(void* const* d_in, const int* in_sizes, int n_in,
                              void* d_out, int out_size)
{
    const int*   word_ids = (const int*)d_in[0];
    const int*   labels   = (const int*)d_in[1];
    const int*   children = (const int*)d_in[2];
    const float* emb = (const float*)d_in[4];
    const float* Wix = (const float*)d_in[5],  *bix = (const float*)d_in[6];
    const float* Wih = (const float*)d_in[7],  *bih = (const float*)d_in[8];
    const float* Wfx = (const float*)d_in[9],  *bfx = (const float*)d_in[10];
    const float* Wfh = (const float*)d_in[11], *bfh = (const float*)d_in[12];
    const float* Wux = (const float*)d_in[13], *bux = (const float*)d_in[14];
    const float* Wuh = (const float*)d_in[15], *buh = (const float*)d_in[16];
    const float* Wout = (const float*)d_in[17], *bout = (const float*)d_in[18];
    float* out = (float*)d_out;

    int pack_elems = WIK * WIROW;   // 389120, largest packed array
    pack_w<<<(pack_elems + 255) / 256, 256>>>(Wix, Wfx, Wux, Wih, Wfh, Wuh,
                                              bix, bfx, bux, bih, bfh, buh);
    mega_kernel<<<NBLK, NTHR>>>(word_ids, labels, children, emb, Wout, bout,
                                out, out_size);
}

// round 8
// speedup vs baseline: 1.1491x; 1.1491x over previous
#include <cuda_runtime.h>
#include <math.h>

#define NN      1023
#define NLEAVES 512
#define HD      300
#define GP      320           // padded per-gate width (strip layout for XX)
#define NBP     960           // 3 * GP
#define NBLK    296           // 2 blocks/SM
#define NTHR    256
#define NJT     19            // ceil(300/16) j-tiles
#define WIROW   1216          // NJT*64 floats per k-row of interleaved weights
#define WIK     320           // padded K rows of interleaved weights

typedef unsigned long long ull;

// ---------------- static device scratch ----------------
__device__ float g_Wxp[HD * NBP];       // W_ix|W_fx|W_ux strips [k][g*320+j]
__device__ float g_Whi[WIK * WIROW];    // interleaved W_*h: [k][jt*64 + jj*4 + g]
__device__ float g_bsum[NBP];           // b_*x + b_*h strips
__device__ float g_XX[NN * NBP];        // x @ Wxp
__device__ float g_h[NN * HD];
__device__ float g_c[NN * HD];
__device__ float g_loss[NN];
__device__ float g_logp_scratch[NN * 5];
__device__ unsigned g_flags[NBLK];

// ---------------- f32x2 helpers ----------------
static __device__ __forceinline__ ull pack2(float x, float y) {
    ull r;
    asm("mov.b64 %0, {%1, %2};" : "=l"(r) : "f"(x), "f"(y));
    return r;
}
static __device__ __forceinline__ void unpack2(ull v, float &x, float &y) {
    asm("mov.b64 {%0, %1}, %2;" : "=f"(x), "=f"(y) : "l"(v));
}
static __device__ __forceinline__ void ffma2(ull &d, ull a, ull b) {
    asm("fma.rn.f32x2 %0, %1, %2, %0;" : "+l"(d) : "l"(a), "l"(b));
}
static __device__ __forceinline__ float sigf(float x) {
    return 1.0f / (1.0f + expf(-x));
}

// ---------------- one-hop all-poll grid barrier ----------------
static __device__ __forceinline__ void gbar(unsigned target) {
    __syncthreads();
    if (threadIdx.x == 0) {
        __threadfence();
        ((volatile unsigned*)g_flags)[blockIdx.x] = target;
    }
    for (int i = threadIdx.x; i < NBLK; i += NTHR)
        while (((volatile unsigned*)g_flags)[i] < target) { }
    __syncthreads();
    if (threadIdx.x == 0) __threadfence();
    __syncthreads();
}

// ---------------- pack weights ----------------
__global__ void pack_w(const float* __restrict__ Wix, const float* __restrict__ Wfx,
                       const float* __restrict__ Wux, const float* __restrict__ Wih,
                       const float* __restrict__ Wfh, const float* __restrict__ Wuh,
                       const float* __restrict__ bix, const float* __restrict__ bfx,
                       const float* __restrict__ bux, const float* __restrict__ bih,
                       const float* __restrict__ bfh, const float* __restrict__ buh)
{
    int idx = blockIdx.x * blockDim.x + threadIdx.x;
    if (idx < HD * NBP) {
        int k = idx / NBP, c = idx % NBP;
        int g = c / GP, j = c % GP;
        float vx = 0.f;
        if (j < HD) {
            const float* wx = (g == 0) ? Wix : (g == 1) ? Wfx : Wux;
            vx = wx[k * HD + j];
        }
        g_Wxp[idx] = vx;
    }
    if (idx < WIK * WIROW) {
        int k = idx / WIROW, rem = idx % WIROW;
        int jt = rem / 64, q = rem % 64;
        int jj = q >> 2, g = q & 3;
        float v = 0.f;
        int j = jt * 16 + jj;
        if (g < 3 && k < HD && j < HD) {
            const float* wh = (g == 0) ? Wih : (g == 1) ? Wfh : Wuh;
            v = wh[k * HD + j];
        }
        g_Whi[idx] = v;
    }
    if (idx < NBP) {
        int g = idx / GP, j = idx % GP;
        float v = 0.f;
        if (j < HD) {
            const float* bx = (g == 0) ? bix : (g == 1) ? bfx : bux;
            const float* bh = (g == 0) ? bih : (g == 1) ? bfh : buh;
            v = bx[j] + bh[j];
        }
        g_bsum[idx] = v;
    }
}

// ---------------- prologue GEMM (strips, 64x64, 4x4 f32x2, double-buffered) -------
static __device__ __forceinline__ void ld_stage_regs(
    const float* __restrict__ aptr, bool aval,
    const float* __restrict__ bptr, size_t bstride, int kb, int akq, int bk,
    float4 &a0, float4 &a1, float4 &b0, float4 &b1)
{
    const float4 z = make_float4(0.f, 0.f, 0.f, 0.f);
    int gk0 = kb + (akq << 2), gk1 = gk0 + 16;
    a0 = (aval && gk0 < HD) ? *(const float4*)(aptr + gk0) : z;
    a1 = (aval && gk1 < HD) ? *(const float4*)(aptr + gk1) : z;
    b0 = *(const float4*)(bptr + (size_t)(kb + bk) * bstride);
    b1 = *(const float4*)(bptr + (size_t)(kb + bk + 16) * bstride);
}

__device__ __noinline__ void gemm_stage(const float* __restrict__ src,
                                        const int* __restrict__ rowIdx, int M,
                                        const float* __restrict__ B,
                                        float* __restrict__ out,
                                        float (&As)[2][32][68],
                                        float (&Bs)[2][32][64])
{
    const int tid = threadIdx.x;
    const int tx = tid & 15, ty = tid >> 4;
    const int am  = tid & 63;
    const int akq = tid >> 6;
    const int bn4 = (tid & 15) << 2;
    const int bk  = tid >> 4;

    const int ntm = (M + 63) >> 6;
    const int ntiles = ntm * 15;
    const int S = 10;

    for (int t = blockIdx.x; t < ntiles; t += NBLK) {
        const int m0 = (t / 15) << 6;
        const int n0 = (t % 15) << 6;

        const bool aval = (m0 + am < M);
        const int  arow = aval ? rowIdx[m0 + am] : 0;
        const float* __restrict__ aptr = src + (size_t)arow * HD;
        const float* __restrict__ bptr = B + n0 + bn4;

        const bool act = (m0 + (ty << 2) < M);

        float4 a0, a1, b0, b1;
        ld_stage_regs(aptr, aval, bptr, NBP, 0, akq, bk, a0, a1, b0, b1);
        {
            int ka = akq << 2;
            As[0][ka + 0][am] = a0.x; As[0][ka + 1][am] = a0.y;
            As[0][ka + 2][am] = a0.z; As[0][ka + 3][am] = a0.w;
            As[0][16 + ka + 0][am] = a1.x; As[0][16 + ka + 1][am] = a1.y;
            As[0][16 + ka + 2][am] = a1.z; As[0][16 + ka + 3][am] = a1.w;
            *(float4*)&Bs[0][bk][bn4]      = b0;
            *(float4*)&Bs[0][bk + 16][bn4] = b1;
        }
        __syncthreads();

        ull acc[4][2];
#pragma unroll
        for (int i = 0; i < 4; i++) { acc[i][0] = pack2(0.f, 0.f); acc[i][1] = pack2(0.f, 0.f); }

        for (int s = 0; s < S; s++) {
            const int p = s & 1;
            if (s + 1 < S)
                ld_stage_regs(aptr, aval, bptr, NBP, (s + 1) << 5, akq, bk, a0, a1, b0, b1);

            if (act) {
                float4 a_c = *(const float4*)&As[p][0][ty << 2];
                ulonglong2 b_c = *(const ulonglong2*)&Bs[p][0][tx << 2];
#pragma unroll
                for (int k = 0; k < 32; k++) {
                    float4 a_n;
                    ulonglong2 b_n;
                    if (k < 31) {
                        a_n = *(const float4*)&As[p][k + 1][ty << 2];
                        b_n = *(const ulonglong2*)&Bs[p][k + 1][tx << 2];
                    } else {
                        a_n = make_float4(0.f, 0.f, 0.f, 0.f);
                        b_n.x = 0; b_n.y = 0;
                    }
                    ull ap;
                    ap = pack2(a_c.x, a_c.x); ffma2(acc[0][0], ap, b_c.x); ffma2(acc[0][1], ap, b_c.y);
                    ap = pack2(a_c.y, a_c.y); ffma2(acc[1][0], ap, b_c.x); ffma2(acc[1][1], ap, b_c.y);
                    ap = pack2(a_c.z, a_c.z); ffma2(acc[2][0], ap, b_c.x); ffma2(acc[2][1], ap, b_c.y);
                    ap = pack2(a_c.w, a_c.w); ffma2(acc[3][0], ap, b_c.x); ffma2(acc[3][1], ap, b_c.y);
                    a_c = a_n; b_c = b_n;
                }
            }

            if (s + 1 < S) {
                const int q = p ^ 1;
                int ka = akq << 2;
                As[q][ka + 0][am] = a0.x; As[q][ka + 1][am] = a0.y;
                As[q][ka + 2][am] = a0.z; As[q][ka + 3][am] = a0.w;
                As[q][16 + ka + 0][am] = a1.x; As[q][16 + ka + 1][am] = a1.y;
                As[q][16 + ka + 2][am] = a1.z; As[q][16 + ka + 3][am] = a1.w;
                *(float4*)&Bs[q][bk][bn4]      = b0;
                *(float4*)&Bs[q][bk + 16][bn4] = b1;
            }
            __syncthreads();
        }

        if (act) {
#pragma unroll
            for (int i = 0; i < 4; i++) {
                int gm = m0 + (ty << 2) + i;
                if (gm < M) {
                    float x0, x1, x2, x3;
                    unpack2(acc[i][0], x0, x1);
                    unpack2(acc[i][1], x2, x3);
                    *(float4*)&out[(size_t)gm * NBP + n0 + (tx << 2)] =
                        make_float4(x0, x1, x2, x3);
                }
            }
        }
    }
}

// ---------------- fused level GEMM: 64x64 tile, interleaved cols, in-reg epilogue --
// A rows = child h-rows (2 per node, adjacent). Tile cols = 16 j's x [i,f,u,pad].
// Thread (ty,tx): rows 4ty..4ty+3 = 2 node pairs, cols = gate triple of j=jt*16+tx.
__device__ __noinline__ void level_fused(int base, int W, const int* __restrict__ children,
                                         float (&As)[2][32][68],
                                         float (&Bs)[2][32][64])
{
    const int tid = threadIdx.x;
    const int tx = tid & 15, ty = tid >> 4;
    const int am  = tid & 63;
    const int akq = tid >> 6;
    const int bn4 = (tid & 15) << 2;
    const int bk  = tid >> 4;

    const int M = 2 * W;
    const int ntm = (M + 63) >> 6;
    const int ntiles = ntm * NJT;
    const int S = 10;
    const int* __restrict__ ch = children + 2 * base;

    for (int t = blockIdx.x; t < ntiles; t += NBLK) {
        const int m0 = (t / NJT) << 6;
        const int jt = t % NJT;

        const bool aval = (m0 + am < M);
        const int  arow = aval ? ch[m0 + am] : 0;
        const float* __restrict__ aptr = g_h + (size_t)arow * HD;
        const float* __restrict__ bptr = g_Whi + jt * 64 + bn4;

        const bool act = (m0 + (ty << 2) < M);

        float4 a0, a1, b0, b1;
        ld_stage_regs(aptr, aval, bptr, WIROW, 0, akq, bk, a0, a1, b0, b1);
        {
            int ka = akq << 2;
            As[0][ka + 0][am] = a0.x; As[0][ka + 1][am] = a0.y;
            As[0][ka + 2][am] = a0.z; As[0][ka + 3][am] = a0.w;
            As[0][16 + ka + 0][am] = a1.x; As[0][16 + ka + 1][am] = a1.y;
            As[0][16 + ka + 2][am] = a1.z; As[0][16 + ka + 3][am] = a1.w;
            *(float4*)&Bs[0][bk][bn4]      = b0;
            *(float4*)&Bs[0][bk + 16][bn4] = b1;
        }
        __syncthreads();

        ull acc[4][2];
#pragma unroll
        for (int i = 0; i < 4; i++) { acc[i][0] = pack2(0.f, 0.f); acc[i][1] = pack2(0.f, 0.f); }

        for (int s = 0; s < S; s++) {
            const int p = s & 1;
            if (s + 1 < S)
                ld_stage_regs(aptr, aval, bptr, WIROW, (s + 1) << 5, akq, bk, a0, a1, b0, b1);

            if (act) {
                float4 a_c = *(const float4*)&As[p][0][ty << 2];
                ulonglong2 b_c = *(const ulonglong2*)&Bs[p][0][tx << 2];
#pragma unroll
                for (int k = 0; k < 32; k++) {
                    float4 a_n;
                    ulonglong2 b_n;
                    if (k < 31) {
                        a_n = *(const float4*)&As[p][k + 1][ty << 2];
                        b_n = *(const ulonglong2*)&Bs[p][k + 1][tx << 2];
                    } else {
                        a_n = make_float4(0.f, 0.f, 0.f, 0.f);
                        b_n.x = 0; b_n.y = 0;
                    }
                    ull ap;
                    ap = pack2(a_c.x, a_c.x); ffma2(acc[0][0], ap, b_c.x); ffma2(acc[0][1], ap, b_c.y);
                    ap = pack2(a_c.y, a_c.y); ffma2(acc[1][0], ap, b_c.x); ffma2(acc[1][1], ap, b_c.y);
                    ap = pack2(a_c.z, a_c.z); ffma2(acc[2][0], ap, b_c.x); ffma2(acc[2][1], ap, b_c.y);
                    ap = pack2(a_c.w, a_c.w); ffma2(acc[3][0], ap, b_c.x); ffma2(acc[3][1], ap, b_c.y);
                    a_c = a_n; b_c = b_n;
                }
            }

            if (s + 1 < S) {
                const int q = p ^ 1;
                int ka = akq << 2;
                As[q][ka + 0][am] = a0.x; As[q][ka + 1][am] = a0.y;
                As[q][ka + 2][am] = a0.z; As[q][ka + 3][am] = a0.w;
                As[q][16 + ka + 0][am] = a1.x; As[q][16 + ka + 1][am] = a1.y;
                As[q][16 + ka + 2][am] = a1.z; As[q][16 + ka + 3][am] = a1.w;
                *(float4*)&Bs[q][bk][bn4]      = b0;
                *(float4*)&Bs[q][bk + 16][bn4] = b1;
            }
            __syncthreads();
        }

        // ---- fused LSTM cell epilogue: 2 node pairs per thread, j = jt*16+tx ----
        const int j = jt * 16 + tx;
        if (act && j < HD) {
#pragma unroll
            for (int pr = 0; pr < 2; pr++) {
                int n = (m0 >> 1) + (ty << 1) + pr;        // node index within level
                if (n < W) {
                    int tn = base + n;
                    float i0, f0g, u0, d0, i1, f1g, u1, d1;
                    unpack2(acc[2 * pr][0],     i0, f0g);
                    unpack2(acc[2 * pr][1],     u0, d0);
                    unpack2(acc[2 * pr + 1][0], i1, f1g);
                    unpack2(acc[2 * pr + 1][1], u1, d1);
                    const float* xx = g_XX + (size_t)tn * NBP;
                    float xi = xx[j]          + g_bsum[j];
                    float xf = xx[GP + j]     + g_bsum[GP + j];
                    float xu = xx[2 * GP + j] + g_bsum[2 * GP + j];
                    float ig = sigf(xi + i0 + i1);
                    float og = sigf(xf + f0g + f1g);
                    float ug = sigf(xu + u0 + u1);
                    float ff0 = sigf(xf + f0g);
                    float ff1 = sigf(xf + f1g);
                    int c0 = children[2 * tn], c1 = children[2 * tn + 1];
                    float cc = ig * ug + ff0 * g_c[c0 * HD + j] + ff1 * g_c[c1 * HD + j];
                    g_c[tn * HD + j] = cc;
                    g_h[tn * HD + j] = og * tanhf(cc);
                }
            }
        }
    }
}

// ---------------- persistent mega-kernel ----------------
__global__ __launch_bounds__(NTHR, 2) void mega_kernel(
    const int* __restrict__ word_ids, const int* __restrict__ labels,
    const int* __restrict__ children, const float* __restrict__ emb,
    const float* __restrict__ Wout, const float* __restrict__ bout,
    float* __restrict__ out, int out_size)
{
    __shared__ float As[2][32][68];
    __shared__ __align__(16) float Bs[2][32][64];
    __shared__ float sred[NTHR];

    unsigned barno = 0;

    // ---- stage 1: prologue GEMM ----
    gemm_stage(emb, word_ids, NN, g_Wxp, g_XX, As, Bs);
    gbar(++barno);

    // ---- stage 2: leaves ----
    for (int idx = blockIdx.x * NTHR + threadIdx.x; idx < NLEAVES * HD; idx += NBLK * NTHR) {
        int t = idx / HD, j = idx % HD;
        const float* xx = g_XX + (size_t)t * NBP;
        float i = sigf(xx[j]          + g_bsum[j]);
        float o = sigf(xx[GP + j]     + g_bsum[GP + j]);
        float u = sigf(xx[2 * GP + j] + g_bsum[2 * GP + j]);
        float c = i * u;
        g_c[t * HD + j] = c;
        g_h[t * HD + j] = o * tanhf(c);
    }
    gbar(++barno);

    // ---- stage 3: 9 fused levels (one pass + one barrier each) ----
    const int bases[9]  = {512, 768, 896, 960, 992, 1008, 1016, 1020, 1022};
    const int widths[9] = {256, 128, 64, 32, 16, 8, 4, 2, 1};
#pragma unroll 1
    for (int l = 0; l < 9; l++) {
        level_fused(bases[l], widths[l], children, As, Bs);
        gbar(++barno);
    }

    // ---- stage 4: logits + log_softmax + per-node loss ----
    {
        int gw = (blockIdx.x * NTHR + threadIdx.x) >> 5;
        int lane = threadIdx.x & 31;
        if (gw < NN) {
            const float* h = g_h + (size_t)gw * HD;
            float a0 = 0.f, a1 = 0.f, a2 = 0.f, a3 = 0.f, a4 = 0.f;
            for (int j = lane; j < HD; j += 32) {
                float hv = h[j];
                const float* w = Wout + j * 5;
                a0 += hv * w[0]; a1 += hv * w[1]; a2 += hv * w[2];
                a3 += hv * w[3]; a4 += hv * w[4];
            }
#pragma unroll
            for (int off = 16; off > 0; off >>= 1) {
                a0 += __shfl_down_sync(0xffffffffu, a0, off);
                a1 += __shfl_down_sync(0xffffffffu, a1, off);
                a2 += __shfl_down_sync(0xffffffffu, a2, off);
                a3 += __shfl_down_sync(0xffffffffu, a3, off);
                a4 += __shfl_down_sync(0xffffffffu, a4, off);
            }
            if (lane == 0) {
                float lg[5] = {a0 + bout[0], a1 + bout[1], a2 + bout[2],
                               a3 + bout[3], a4 + bout[4]};
                float mx = lg[0];
#pragma unroll
                for (int l = 1; l < 5; l++) mx = fmaxf(mx, lg[l]);
                float se = 0.f;
#pragma unroll
                for (int l = 0; l < 5; l++) se += expf(lg[l] - mx);
                float lse = mx + logf(se);
                float* dst = (out_size >= NN * 5) ? (out + (size_t)gw * 5)
                                                  : (g_logp_scratch + (size_t)gw * 5);
#pragma unroll
                for (int l = 0; l < 5; l++) dst[l] = lg[l] - lse;
                g_loss[gw] = -(lg[labels[gw]] - lse);
            }
        }
    }

    // ---- final barrier: arrival-only; block 0 reduces loss and resets flags ----
    {
        const unsigned fin = ++barno;
        __syncthreads();
        if (threadIdx.x == 0) {
            __threadfence();
            ((volatile unsigned*)g_flags)[blockIdx.x] = fin;
        }
        if (blockIdx.x != 0) return;

        for (int i = threadIdx.x; i < NBLK; i += NTHR)
            while (((volatile unsigned*)g_flags)[i] < fin) { }
        __syncthreads();
        if (threadIdx.x == 0) __threadfence();
        __syncthreads();

        float v = 0.f;
        for (int i = threadIdx.x; i < NN; i += NTHR) v += g_loss[i];
        sred[threadIdx.x] = v;
        __syncthreads();
        for (int st = NTHR / 2; st > 0; st >>= 1) {
            if (threadIdx.x < st) sred[threadIdx.x] += sred[threadIdx.x + st];
            __syncthreads();
        }
        if (threadIdx.x == 0) {
            if (out_size > NN * 5)      out[NN * 5] = sred[0];
            else if (out_size < NN * 5) out[0]      = sred[0];
        }
        __syncthreads();

        for (int i = threadIdx.x; i < NBLK; i += NTHR)
            ((volatile unsigned*)g_flags)[i] = 0;
        if (threadIdx.x == 0) __threadfence();
    }
}

// ---------------- launch ----------------
extern "C" void kernel_launch(void* const* d_in, const int* in_sizes, int n_in,
                              void* d_out, int out_size)
{
    const int*   word_ids = (const int*)d_in[0];
    const int*   labels   = (const int*)d_in[1];
    const int*   children = (const int*)d_in[2];
    const float* emb = (const float*)d_in[4];
    const float* Wix = (const float*)d_in[5],  *bix = (const float*)d_in[6];
    const float* Wih = (const float*)d_in[7],  *bih = (const float*)d_in[8];
    const float* Wfx = (const float*)d_in[9],  *bfx = (const float*)d_in[10];
    const float* Wfh = (const float*)d_in[11], *bfh = (const float*)d_in[12];
    const float* Wux = (const float*)d_in[13], *bux = (const float*)d_in[14];
    const float* Wuh = (const float*)d_in[15], *buh = (const float*)d_in[16];
    const float* Wout = (const float*)d_in[17], *bout = (const float*)d_in[18];
    float* out = (float*)d_out;

    int pack_elems = WIK * WIROW;   // 389120 — largest packed array
    pack_w<<<(pack_elems + 255) / 256, 256>>>(Wix, Wfx, Wux, Wih, Wfh, Wuh,
                                              bix, bfx, bux, bih, bfh, buh);
    mega_kernel<<<NBLK, NTHR>>>(word_ids, labels, children, emb, Wout, bout,
                                out, out_size);
}